// round 14
// baseline (speedup 1.0000x reference)
#include <cuda_runtime.h>

#define B_   4
#define N_   4096
#define K_   512
#define NT   64                 // children per CTA
#define GRID_X (N_/NT)          // 64
#define GRID_TOTAL (GRID_X*B_)  // 256
#define NTHR 256                // thread owns parents 2*tid, 2*tid+1 (f32x2 lanes)
#define DEPTH 8                 // A prefetch depth (rows)
#define EPSF 1e-6f

typedef unsigned long long ull;

__device__ double   g_blkP[GRID_TOTAL];
__device__ double   g_blkC[GRID_TOTAL];
__device__ float    g_blkM[GRID_TOTAL];
__device__ unsigned g_cnt;   // zero-init; atomicInc wrap resets each launch

__device__ __forceinline__ ull pack2(float lo, float hi) {
    ull r; asm("mov.b64 %0, {%1, %2};" : "=l"(r) : "f"(lo), "f"(hi)); return r;
}
__device__ __forceinline__ float2 unpack2(ull v) {
    float2 r; asm("mov.b64 {%0, %1}, %2;" : "=f"(r.x), "=f"(r.y) : "l"(v)); return r;
}
__device__ __forceinline__ ull fma2(ull a, ull b, ull c) {
    ull d; asm("fma.rn.f32x2 %0, %1, %2, %3;" : "=l"(d) : "l"(a), "l"(b), "l"(c)); return d;
}
__device__ __forceinline__ ull mul2(ull a, ull b) {
    ull d; asm("mul.rn.f32x2 %0, %1, %2;" : "=l"(d) : "l"(a), "l"(b)); return d;
}
__device__ __forceinline__ ull add2(ull a, ull b) {
    ull d; asm("add.rn.f32x2 %0, %1, %2;" : "=l"(d) : "l"(a), "l"(b)); return d;
}

// symmetric 3x3 inverse of (S + eps*I)
__device__ __forceinline__ void inv3sym(const float* __restrict__ S,
                                        float& i00, float& i01, float& i02,
                                        float& i11, float& i12, float& i22) {
    float s00 = S[0] + EPSF, s01 = S[1], s02 = S[2];
    float s11 = S[4] + EPSF, s12 = S[5];
    float s22 = S[8] + EPSF;
    float c00 = s11 * s22 - s12 * s12;
    float c01 = s02 * s12 - s01 * s22;
    float c02 = s01 * s12 - s02 * s11;
    float c11 = s00 * s22 - s02 * s02;
    float c12 = s01 * s02 - s00 * s12;
    float c22 = s00 * s11 - s01 * s01;
    float det = s00 * c00 + s01 * c01 + s02 * c02;
    float id  = 1.0f / det;
    i00 = c00 * id; i01 = c01 * id; i02 = c02 * id;
    i11 = c11 * id; i12 = c12 * id; i22 = c22 * id;
}

__global__ void __launch_bounds__(NTHR, 2)
loss_kernel(const float* __restrict__ muC, const float* __restrict__ SC,
            const float* __restrict__ muP, const float* __restrict__ SP,
            const float* __restrict__ A,   const float* __restrict__ mask,
            float* __restrict__ out)
{
    // per child n: 10 SCALAR features (no duplication), 40B:
    // c0,c1,c2, J00,J11,J22, 2J01,2J02,2J12, m
    __shared__ float shF[NT * 10];
    __shared__ float redP[8], redC[8];
    __shared__ float sMask;
    __shared__ int   sLast;

    const int b   = blockIdx.y;
    const int n0  = blockIdx.x * NT;
    const int tid = threadIdx.x;
    const int k0  = 2 * tid;

    // ---- parent-pair features, packed {k0, k1} (9 ull = 18 regs) ----
    float a00, a01, a02, a11, a12, a22;
    float b00, b01, b02, b11, b12, b22;
    inv3sym(SP + (size_t)(b * K_ + k0) * 9,     a00, a01, a02, a11, a12, a22);
    inv3sym(SP + (size_t)(b * K_ + k0 + 1) * 9, b00, b01, b02, b11, b12, b22);
    const float* mpA = muP + (size_t)(b * K_ + k0) * 3;
    const float* mpB = muP + (size_t)(b * K_ + k0 + 1) * 3;
    ull Pn0  = pack2(-mpA[0], -mpB[0]);
    ull Pn1  = pack2(-mpA[1], -mpB[1]);
    ull Pn2  = pack2(-mpA[2], -mpB[2]);
    ull PI00 = pack2(a00, b00);
    ull PI11 = pack2(a11, b11);
    ull PI22 = pack2(a22, b22);
    ull PI01 = pack2(2.f * a01, 2.f * b01);
    ull PI02 = pack2(2.f * a02, 2.f * b02);
    ull PI12 = pack2(2.f * a12, 2.f * b12);

    // ---- child features -> shared (scalar, 40B per child) ----
    if (tid < NT) {
        int n = n0 + tid;
        float j00, j01, j02, j11, j12, j22;
        inv3sym(SC + (size_t)(b * N_ + n) * 9, j00, j01, j02, j11, j12, j22);
        const float* mc = muC + (size_t)(b * N_ + n) * 3;
        float* d = &shF[tid * 10];
        d[0] = mc[0];      d[1] = mc[1];      d[2] = mc[2];
        d[3] = j00;        d[4] = j11;        d[5] = j22;
        d[6] = 2.f * j01;  d[7] = 2.f * j02;  d[8] = 2.f * j12;
        d[9] = mask[b * N_ + n];
    }
    __syncthreads();

    // block mask partial: warp 0, lane i owns children i, i+32
    if (tid < 32) {
        float m = shF[tid * 10 + 9] + shF[(tid + 32) * 10 + 9];
#pragma unroll
        for (int off = 16; off; off >>= 1)
            m += __shfl_down_sync(0xffffffffu, m, off);
        if (tid == 0) sMask = m;
    }

    // A row n, parents (k0, k0+1) adjacent: one float2 per row
    const float2* Ap = (const float2*)(A + ((size_t)b * N_ + n0) * K_) + tid;

    float2 abuf[DEPTH];
#pragma unroll
    for (int i = 0; i < DEPTH; i++) abuf[i] = __ldcs(Ap + i * (K_ / 2));

    ull accP = 0ull, accC = 0ull;

#pragma unroll
    for (int n = 0; n < NT; ++n) {
        float2 av = abuf[n & (DEPTH - 1)];
        if (n < NT - DEPTH)
            abuf[n & (DEPTH - 1)] = __ldcs(Ap + (size_t)(n + DEPTH) * (K_ / 2));

        // ---- scalar broadcast loads (1 wavefront each), pack to {v,v} ----
        const float* f = &shF[n * 10];
        float  vc0 = f[0], vc1 = f[1], vc2 = f[2];
        float  vj00 = f[3], vj11 = f[4], vj22 = f[5];
        float  vj01 = f[6], vj02 = f[7], vj12 = f[8];
        float  vm   = f[9];
        ull Fc0  = pack2(vc0, vc0);
        ull Fc1  = pack2(vc1, vc1);
        ull Fc2  = pack2(vc2, vc2);
        ull FJ00 = pack2(vj00, vj00);
        ull FJ11 = pack2(vj11, vj11);
        ull FJ22 = pack2(vj22, vj22);
        ull FJ01 = pack2(vj01, vj01);
        ull FJ02 = pack2(vj02, vj02);
        ull FJ12 = pack2(vj12, vj12);

        ull d0 = add2(Fc0, Pn0);      // {c - p(k0), c - p(k1)}
        ull d1 = add2(Fc1, Pn1);
        ull d2 = add2(Fc2, Pn2);

        ull dd, mp, mc;
        dd = mul2(d0, d0);
        mp = mul2(dd, PI00);      mc = mul2(dd, FJ00);
        dd = mul2(d1, d1);
        mp = fma2(dd, PI11, mp);  mc = fma2(dd, FJ11, mc);
        dd = mul2(d2, d2);
        mp = fma2(dd, PI22, mp);  mc = fma2(dd, FJ22, mc);
        dd = mul2(d0, d1);
        mp = fma2(dd, PI01, mp);  mc = fma2(dd, FJ01, mc);
        dd = mul2(d0, d2);
        mp = fma2(dd, PI02, mp);  mc = fma2(dd, FJ02, mc);
        dd = mul2(d1, d2);
        mp = fma2(dd, PI12, mp);  mc = fma2(dd, FJ12, mc);

        ull am = mul2(pack2(av.x, av.y), pack2(vm, vm));   // {A(n,k0),A(n,k1)}*mask
        accP = fma2(am, mp, accP);
        accC = fma2(am, mc, accC);
    }

    // ---- in-block reduction ----
    float2 vP = unpack2(accP), vC = unpack2(accC);
    float sp = vP.x + vP.y;
    float sc = vC.x + vC.y;
#pragma unroll
    for (int off = 16; off; off >>= 1) {
        sp += __shfl_down_sync(0xffffffffu, sp, off);
        sc += __shfl_down_sync(0xffffffffu, sc, off);
    }
    int wid = tid >> 5, lane = tid & 31;
    if (lane == 0) { redP[wid] = sp; redC[wid] = sc; }
    __syncthreads();

    const int bid = blockIdx.y * gridDim.x + blockIdx.x;
    if (tid == 0) {
        float tp = 0.f, tc = 0.f;
#pragma unroll
        for (int i = 0; i < 8; i++) { tp += redP[i]; tc += redC[i]; }
        g_blkP[bid] = (double)tp;
        g_blkC[bid] = (double)tc;
        g_blkM[bid] = sMask;
        __threadfence();
        unsigned t = atomicInc(&g_cnt, GRID_TOTAL - 1);
        sLast = (t == GRID_TOTAL - 1);
    }
    __syncthreads();

    // ---- last block: final reduction + output ----
    if (sLast) {
        __threadfence();
        __shared__ double fP[8], fC[8];
        __shared__ float  fM[8];
        double p = g_blkP[tid];   // 256 slots, 256 threads
        double c = g_blkC[tid];
        float  m = g_blkM[tid];
#pragma unroll
        for (int off = 16; off; off >>= 1) {
            p += __shfl_down_sync(0xffffffffu, p, off);
            c += __shfl_down_sync(0xffffffffu, c, off);
            m += __shfl_down_sync(0xffffffffu, m, off);
        }
        if (lane == 0) { fP[wid] = p; fC[wid] = c; fM[wid] = m; }
        __syncthreads();
        if (tid == 0) {
            double tp = 0.0, tc = 0.0;
            float  tm = 0.f;
#pragma unroll
            for (int i = 0; i < 8; i++) { tp += fP[i]; tc += fC[i]; tm += fM[i]; }
            double denom = (tm > 1.f) ? (double)tm : 1.0;
            out[0] = (float)((tp + tc) / denom);  // final_loss
            out[1] = (float)(tp / denom);          // dist_p_m
            out[2] = (float)(tc / denom);          // dist_c_m
        }
    }
}

extern "C" void kernel_launch(void* const* d_in, const int* in_sizes, int n_in,
                              void* d_out, int out_size) {
    const float* muC  = (const float*)d_in[0];
    const float* SC   = (const float*)d_in[1];
    const float* muP  = (const float*)d_in[2];
    const float* SP   = (const float*)d_in[3];
    const float* A    = (const float*)d_in[4];
    const float* mask = (const float*)d_in[5];

    dim3 grid(GRID_X, B_);
    loss_kernel<<<grid, NTHR>>>(muC, SC, muP, SP, A, mask, (float*)d_out);
}

// round 15
// speedup vs baseline: 1.0583x; 1.0583x over previous
#include <cuda_runtime.h>

#define B_   4
#define N_   4096
#define K_   512
#define NSPLIT 16               // n-slices
#define NSL  256                // n's per CTA
#define NCHUNK (NSL/8)          // 32 K-steps
#define NTHR 256
#define GRID_TOTAL (B_*4*NSPLIT)   // 256
#define CFS 260                 // CF_T row stride (floats) -> conflict-free frag LDS
#define GSS 25                  // Gs row stride
#define EPSF 1e-6f

__device__ double   g_blkP[GRID_TOTAL];
__device__ double   g_blkC[GRID_TOTAL];
__device__ float    g_blkM[GRID_TOTAL];
__device__ unsigned g_cnt;   // zero-init; atomicInc wrap resets each launch

__device__ __forceinline__ unsigned f2tf32(float x) {
    unsigned r; asm("cvt.rna.tf32.f32 %0, %1;" : "=r"(r) : "f"(x)); return r;
}

// symmetric 3x3 inverse of (S + eps*I)
__device__ __forceinline__ void inv3sym(const float* __restrict__ S,
                                        float& i00, float& i01, float& i02,
                                        float& i11, float& i12, float& i22) {
    float s00 = S[0] + EPSF, s01 = S[1], s02 = S[2];
    float s11 = S[4] + EPSF, s12 = S[5];
    float s22 = S[8] + EPSF;
    float c00 = s11 * s22 - s12 * s12;
    float c01 = s02 * s12 - s01 * s22;
    float c02 = s01 * s12 - s02 * s11;
    float c11 = s00 * s22 - s02 * s02;
    float c12 = s01 * s02 - s00 * s12;
    float c22 = s00 * s11 - s01 * s01;
    float det = s00 * c00 + s01 * c01 + s02 * c02;
    float id  = 1.0f / det;
    i00 = c00 * id; i01 = c01 * id; i02 = c02 * id;
    i11 = c11 * id; i12 = c12 * id; i22 = c22 * id;
}

__global__ void __launch_bounds__(NTHR)
loss_kernel(const float* __restrict__ muC, const float* __restrict__ SC,
            const float* __restrict__ muP, const float* __restrict__ SP,
            const float* __restrict__ A,   const float* __restrict__ mask,
            float* __restrict__ out)
{
    __shared__ float cfT[24 * CFS];      // CF transposed [feature][n], tf32-rounded
    __shared__ float Gs[128 * GSS];      // per-CTA moment sums [k_local][feature]
    __shared__ float redP[8], redC[8], redM[8];
    __shared__ int   sLast;

    const int x   = blockIdx.x;          // n-slice
    const int kg  = blockIdx.y;          // k-group (128 parents)
    const int b   = blockIdx.z;
    const int tid = threadIdx.x;
    const int wid = tid >> 5;
    const int lane = tid & 31;
    const int gid = lane >> 2;           // 0..7
    const int tig = lane & 3;            // 0..3

    // ---- prologue: build 20 masked features for n = x*NSL + tid ----
    float mval;
    {
        int n = x * NSL + tid;
        float j00, j01, j02, j11, j12, j22;
        inv3sym(SC + (size_t)(b * N_ + n) * 9, j00, j01, j02, j11, j12, j22);
        const float* mc = muC + (size_t)(b * N_ + n) * 3;
        float c0 = mc[0], c1 = mc[1], c2 = mc[2];
        float u0 = j00 * c0 + j01 * c1 + j02 * c2;
        float u1 = j01 * c0 + j11 * c1 + j12 * c2;
        float u2 = j02 * c0 + j12 * c1 + j22 * c2;
        float t  = c0 * u0 + c1 * u1 + c2 * u2;
        float m  = mask[b * N_ + n];
        mval = m;
        float f[24];
        f[0] = m*c0*c0;  f[1] = m*c1*c1;  f[2] = m*c2*c2;
        f[3] = m*c0*c1;  f[4] = m*c0*c2;  f[5] = m*c1*c2;
        f[6] = m*c0;     f[7] = m*c1;     f[8] = m*c2;
        f[9] = m;
        f[10] = m*j00;       f[11] = m*j11;       f[12] = m*j22;
        f[13] = m*2.f*j01;   f[14] = m*2.f*j02;   f[15] = m*2.f*j12;
        f[16] = m*u0;        f[17] = m*u1;        f[18] = m*u2;
        f[19] = m*t;
        f[20] = 0.f; f[21] = 0.f; f[22] = 0.f; f[23] = 0.f;
#pragma unroll
        for (int i = 0; i < 24; i++)
            cfT[i * CFS + tid] = __uint_as_float(f2tf32(f[i]));
    }
    __syncthreads();

    // ---- main loop: warp owns 16 parents, 24 features; contract 256 n's ----
    const int kbase = kg * 128 + wid * 16;
    const float* gA = A + ((size_t)(b * N_ + x * NSL)) * K_ + kbase + gid;

    float d0[4] = {0.f, 0.f, 0.f, 0.f};
    float d1[4] = {0.f, 0.f, 0.f, 0.f};
    float d2[4] = {0.f, 0.f, 0.f, 0.f};

#pragma unroll 4
    for (int c = 0; c < NCHUNK; ++c) {
        int r0 = c * 8 + tig;
        int r1 = r0 + 4;
        // A fragment (m16n8k8 row-major): rows = parents, cols = n
        float a0f = __ldcs(gA + (size_t)r0 * K_);
        float a1f = __ldcs(gA + (size_t)r0 * K_ + 8);
        float a2f = __ldcs(gA + (size_t)r1 * K_);
        float a3f = __ldcs(gA + (size_t)r1 * K_ + 8);
        unsigned ua0 = f2tf32(a0f), ua1 = f2tf32(a1f);
        unsigned ua2 = f2tf32(a2f), ua3 = f2tf32(a3f);

        // B fragments (col-major 8x8): row = n-contraction, col = feature
        int nb = c * 8 + tig;
        unsigned b00 = __float_as_uint(cfT[(gid)      * CFS + nb]);
        unsigned b01 = __float_as_uint(cfT[(gid)      * CFS + nb + 4]);
        unsigned b10 = __float_as_uint(cfT[(8 + gid)  * CFS + nb]);
        unsigned b11 = __float_as_uint(cfT[(8 + gid)  * CFS + nb + 4]);
        unsigned b20 = __float_as_uint(cfT[(16 + gid) * CFS + nb]);
        unsigned b21 = __float_as_uint(cfT[(16 + gid) * CFS + nb + 4]);

        asm("mma.sync.aligned.m16n8k8.row.col.f32.tf32.tf32.f32 "
            "{%0,%1,%2,%3}, {%4,%5,%6,%7}, {%8,%9}, {%0,%1,%2,%3};"
            : "+f"(d0[0]), "+f"(d0[1]), "+f"(d0[2]), "+f"(d0[3])
            : "r"(ua0), "r"(ua1), "r"(ua2), "r"(ua3), "r"(b00), "r"(b01));
        asm("mma.sync.aligned.m16n8k8.row.col.f32.tf32.tf32.f32 "
            "{%0,%1,%2,%3}, {%4,%5,%6,%7}, {%8,%9}, {%0,%1,%2,%3};"
            : "+f"(d1[0]), "+f"(d1[1]), "+f"(d1[2]), "+f"(d1[3])
            : "r"(ua0), "r"(ua1), "r"(ua2), "r"(ua3), "r"(b10), "r"(b11));
        asm("mma.sync.aligned.m16n8k8.row.col.f32.tf32.tf32.f32 "
            "{%0,%1,%2,%3}, {%4,%5,%6,%7}, {%8,%9}, {%0,%1,%2,%3};"
            : "+f"(d2[0]), "+f"(d2[1]), "+f"(d2[2]), "+f"(d2[3])
            : "r"(ua0), "r"(ua1), "r"(ua2), "r"(ua3), "r"(b20), "r"(b21));
    }
    __syncthreads();   // cfT reads done; Gs may alias usage pattern below

    // ---- store D fragments -> Gs[k_local][feature] ----
    {
        int row = wid * 16 + gid;
        Gs[row * GSS + tig * 2]          = d0[0];
        Gs[row * GSS + tig * 2 + 1]      = d0[1];
        Gs[(row + 8) * GSS + tig * 2]    = d0[2];
        Gs[(row + 8) * GSS + tig * 2 + 1]= d0[3];
        Gs[row * GSS + 8 + tig * 2]          = d1[0];
        Gs[row * GSS + 8 + tig * 2 + 1]      = d1[1];
        Gs[(row + 8) * GSS + 8 + tig * 2]    = d1[2];
        Gs[(row + 8) * GSS + 8 + tig * 2 + 1]= d1[3];
        Gs[row * GSS + 16 + tig * 2]          = d2[0];
        Gs[row * GSS + 16 + tig * 2 + 1]      = d2[1];
        Gs[(row + 8) * GSS + 16 + tig * 2]    = d2[2];
        Gs[(row + 8) * GSS + 16 + tig * 2 + 1]= d2[3];
    }
    __syncthreads();

    // ---- epilogue: fold G with parent features (threads 0..127, one k each) ----
    float sp = 0.f, sc = 0.f;
    if (tid < 128) {
        int k = kg * 128 + tid;
        float i00, i01, i02, i11, i12, i22;
        inv3sym(SP + (size_t)(b * K_ + k) * 9, i00, i01, i02, i11, i12, i22);
        const float* mp = muP + (size_t)(b * K_ + k) * 3;
        float p0 = mp[0], p1 = mp[1], p2 = mp[2];
        float w0 = i00 * p0 + i01 * p1 + i02 * p2;
        float w1 = i01 * p0 + i11 * p1 + i12 * p2;
        float w2 = i02 * p0 + i12 * p1 + i22 * p2;
        float r  = p0 * w0 + p1 * w1 + p2 * w2;
        const float* g = &Gs[tid * GSS];
        sp = g[0]*i00 + g[1]*i11 + g[2]*i22
           + 2.f*(g[3]*i01 + g[4]*i02 + g[5]*i12)
           - 2.f*(g[6]*w0 + g[7]*w1 + g[8]*w2)
           + g[9]*r;
        sc = g[10]*p0*p0 + g[11]*p1*p1 + g[12]*p2*p2
           + g[13]*p0*p1 + g[14]*p0*p2 + g[15]*p1*p2
           - 2.f*(g[16]*p0 + g[17]*p1 + g[18]*p2)
           + g[19];
    }
    float mv = (kg == 0) ? mval : 0.f;   // count each mask element once

    // ---- in-block reduction ----
#pragma unroll
    for (int off = 16; off; off >>= 1) {
        sp += __shfl_down_sync(0xffffffffu, sp, off);
        sc += __shfl_down_sync(0xffffffffu, sc, off);
        mv += __shfl_down_sync(0xffffffffu, mv, off);
    }
    if (lane == 0) { redP[wid] = sp; redC[wid] = sc; redM[wid] = mv; }
    __syncthreads();

    const int bid = (b * 4 + kg) * NSPLIT + x;
    if (tid == 0) {
        float tp = 0.f, tc = 0.f, tm = 0.f;
#pragma unroll
        for (int i = 0; i < 8; i++) { tp += redP[i]; tc += redC[i]; tm += redM[i]; }
        g_blkP[bid] = (double)tp;
        g_blkC[bid] = (double)tc;
        g_blkM[bid] = tm;
        __threadfence();
        unsigned t = atomicInc(&g_cnt, GRID_TOTAL - 1);
        sLast = (t == GRID_TOTAL - 1);
    }
    __syncthreads();

    // ---- last block: final reduction + output ----
    if (sLast) {
        __threadfence();
        __shared__ double fP[8], fC[8];
        __shared__ float  fM[8];
        double p = g_blkP[tid];   // 256 slots, 256 threads
        double c = g_blkC[tid];
        float  m = g_blkM[tid];
#pragma unroll
        for (int off = 16; off; off >>= 1) {
            p += __shfl_down_sync(0xffffffffu, p, off);
            c += __shfl_down_sync(0xffffffffu, c, off);
            m += __shfl_down_sync(0xffffffffu, m, off);
        }
        if (lane == 0) { fP[wid] = p; fC[wid] = c; fM[wid] = m; }
        __syncthreads();
        if (tid == 0) {
            double tp = 0.0, tc = 0.0;
            float  tm = 0.f;
#pragma unroll
            for (int i = 0; i < 8; i++) { tp += fP[i]; tc += fC[i]; tm += fM[i]; }
            double denom = (tm > 1.f) ? (double)tm : 1.0;
            out[0] = (float)((tp + tc) / denom);  // final_loss
            out[1] = (float)(tp / denom);          // dist_p_m
            out[2] = (float)(tc / denom);          // dist_c_m
        }
    }
}

extern "C" void kernel_launch(void* const* d_in, const int* in_sizes, int n_in,
                              void* d_out, int out_size) {
    const float* muC  = (const float*)d_in[0];
    const float* SC   = (const float*)d_in[1];
    const float* muP  = (const float*)d_in[2];
    const float* SP   = (const float*)d_in[3];
    const float* A    = (const float*)d_in[4];
    const float* mask = (const float*)d_in[5];

    dim3 grid(NSPLIT, 4, B_);
    loss_kernel<<<grid, NTHR>>>(muC, SC, muP, SP, A, mask, (float*)d_out);
}

// round 16
// speedup vs baseline: 1.1345x; 1.0720x over previous
#include <cuda_runtime.h>

#define B_   4
#define N_   4096
#define K_   512
#define NSPLIT 16               // n-slices
#define NSL  256                // n's per CTA
#define NCHUNK (NSL/8)          // 32 K-steps
#define NTHR 256
#define GRID_TOTAL (B_*4*NSPLIT)   // 256
#define CFS 260                 // CF_T row stride (floats) -> conflict-free frag LDS
#define GSS 25                  // Gs row stride
#define EPSF 1e-6f

__device__ double   g_blkP[GRID_TOTAL];
__device__ double   g_blkC[GRID_TOTAL];
__device__ float    g_blkM[GRID_TOTAL];
__device__ unsigned g_cnt;   // zero-init; atomicInc wrap resets each launch

__device__ __forceinline__ unsigned f2tf32(float x) {
    unsigned r; asm("cvt.rna.tf32.f32 %0, %1;" : "=r"(r) : "f"(x)); return r;
}

// symmetric 3x3 inverse of (S + eps*I)
__device__ __forceinline__ void inv3sym(const float* __restrict__ S,
                                        float& i00, float& i01, float& i02,
                                        float& i11, float& i12, float& i22) {
    float s00 = S[0] + EPSF, s01 = S[1], s02 = S[2];
    float s11 = S[4] + EPSF, s12 = S[5];
    float s22 = S[8] + EPSF;
    float c00 = s11 * s22 - s12 * s12;
    float c01 = s02 * s12 - s01 * s22;
    float c02 = s01 * s12 - s02 * s11;
    float c11 = s00 * s22 - s02 * s02;
    float c12 = s01 * s02 - s00 * s12;
    float c22 = s00 * s11 - s01 * s01;
    float det = s00 * c00 + s01 * c01 + s02 * c02;
    float id  = 1.0f / det;
    i00 = c00 * id; i01 = c01 * id; i02 = c02 * id;
    i11 = c11 * id; i12 = c12 * id; i22 = c22 * id;
}

__global__ void __launch_bounds__(NTHR)
loss_kernel(const float* __restrict__ muC, const float* __restrict__ SC,
            const float* __restrict__ muP, const float* __restrict__ SP,
            const float* __restrict__ A,   const float* __restrict__ mask,
            float* __restrict__ out)
{
    __shared__ float cfT[24 * CFS];      // CF transposed [feature][n], tf32-rounded
    __shared__ float Gs[128 * GSS];      // per-CTA moment sums [k_local][feature]
    __shared__ float redP[8], redC[8], redM[8];
    __shared__ int   sLast;

    const int x   = blockIdx.x;          // n-slice
    const int kg  = blockIdx.y;          // k-group (128 parents)
    const int b   = blockIdx.z;
    const int tid = threadIdx.x;
    const int wid = tid >> 5;
    const int lane = tid & 31;
    const int gid = lane >> 2;           // 0..7
    const int tig = lane & 3;            // 0..3

    // ---- prologue: build 20 masked features for n = x*NSL + tid ----
    float mval;
    {
        int n = x * NSL + tid;
        float j00, j01, j02, j11, j12, j22;
        inv3sym(SC + (size_t)(b * N_ + n) * 9, j00, j01, j02, j11, j12, j22);
        const float* mc = muC + (size_t)(b * N_ + n) * 3;
        float c0 = mc[0], c1 = mc[1], c2 = mc[2];
        float u0 = j00 * c0 + j01 * c1 + j02 * c2;
        float u1 = j01 * c0 + j11 * c1 + j12 * c2;
        float u2 = j02 * c0 + j12 * c1 + j22 * c2;
        float t  = c0 * u0 + c1 * u1 + c2 * u2;
        float m  = mask[b * N_ + n];
        mval = m;
        float f[24];
        f[0] = m*c0*c0;  f[1] = m*c1*c1;  f[2] = m*c2*c2;
        f[3] = m*c0*c1;  f[4] = m*c0*c2;  f[5] = m*c1*c2;
        f[6] = m*c0;     f[7] = m*c1;     f[8] = m*c2;
        f[9] = m;
        f[10] = m*j00;       f[11] = m*j11;       f[12] = m*j22;
        f[13] = m*2.f*j01;   f[14] = m*2.f*j02;   f[15] = m*2.f*j12;
        f[16] = m*u0;        f[17] = m*u1;        f[18] = m*u2;
        f[19] = m*t;
        f[20] = 0.f; f[21] = 0.f; f[22] = 0.f; f[23] = 0.f;
#pragma unroll
        for (int i = 0; i < 24; i++)
            cfT[i * CFS + tid] = __uint_as_float(f2tf32(f[i]));
    }
    __syncthreads();

    // ---- main loop: warp owns 16 parents, 24 features; contract 256 n's ----
    const int kbase = kg * 128 + wid * 16;
    const float* gA = A + ((size_t)(b * N_ + x * NSL)) * K_ + kbase + gid;

    float d0[4] = {0.f, 0.f, 0.f, 0.f};
    float d1[4] = {0.f, 0.f, 0.f, 0.f};
    float d2[4] = {0.f, 0.f, 0.f, 0.f};

#pragma unroll 4
    for (int c = 0; c < NCHUNK; ++c) {
        int r0 = c * 8 + tig;
        int r1 = r0 + 4;
        // A fragment (m16n8k8 row-major): rows = parents, cols = n
        float a0f = __ldcs(gA + (size_t)r0 * K_);
        float a1f = __ldcs(gA + (size_t)r0 * K_ + 8);
        float a2f = __ldcs(gA + (size_t)r1 * K_);
        float a3f = __ldcs(gA + (size_t)r1 * K_ + 8);
        unsigned ua0 = f2tf32(a0f), ua1 = f2tf32(a1f);
        unsigned ua2 = f2tf32(a2f), ua3 = f2tf32(a3f);

        // B fragments (col-major 8x8): row = n-contraction, col = feature
        int nb = c * 8 + tig;
        unsigned b00 = __float_as_uint(cfT[(gid)      * CFS + nb]);
        unsigned b01 = __float_as_uint(cfT[(gid)      * CFS + nb + 4]);
        unsigned b10 = __float_as_uint(cfT[(8 + gid)  * CFS + nb]);
        unsigned b11 = __float_as_uint(cfT[(8 + gid)  * CFS + nb + 4]);
        unsigned b20 = __float_as_uint(cfT[(16 + gid) * CFS + nb]);
        unsigned b21 = __float_as_uint(cfT[(16 + gid) * CFS + nb + 4]);

        asm("mma.sync.aligned.m16n8k8.row.col.f32.tf32.tf32.f32 "
            "{%0,%1,%2,%3}, {%4,%5,%6,%7}, {%8,%9}, {%0,%1,%2,%3};"
            : "+f"(d0[0]), "+f"(d0[1]), "+f"(d0[2]), "+f"(d0[3])
            : "r"(ua0), "r"(ua1), "r"(ua2), "r"(ua3), "r"(b00), "r"(b01));
        asm("mma.sync.aligned.m16n8k8.row.col.f32.tf32.tf32.f32 "
            "{%0,%1,%2,%3}, {%4,%5,%6,%7}, {%8,%9}, {%0,%1,%2,%3};"
            : "+f"(d1[0]), "+f"(d1[1]), "+f"(d1[2]), "+f"(d1[3])
            : "r"(ua0), "r"(ua1), "r"(ua2), "r"(ua3), "r"(b10), "r"(b11));
        asm("mma.sync.aligned.m16n8k8.row.col.f32.tf32.tf32.f32 "
            "{%0,%1,%2,%3}, {%4,%5,%6,%7}, {%8,%9}, {%0,%1,%2,%3};"
            : "+f"(d2[0]), "+f"(d2[1]), "+f"(d2[2]), "+f"(d2[3])
            : "r"(ua0), "r"(ua1), "r"(ua2), "r"(ua3), "r"(b20), "r"(b21));
    }
    __syncthreads();   // cfT reads done; Gs may alias usage pattern below

    // ---- store D fragments -> Gs[k_local][feature] ----
    {
        int row = wid * 16 + gid;
        Gs[row * GSS + tig * 2]          = d0[0];
        Gs[row * GSS + tig * 2 + 1]      = d0[1];
        Gs[(row + 8) * GSS + tig * 2]    = d0[2];
        Gs[(row + 8) * GSS + tig * 2 + 1]= d0[3];
        Gs[row * GSS + 8 + tig * 2]          = d1[0];
        Gs[row * GSS + 8 + tig * 2 + 1]      = d1[1];
        Gs[(row + 8) * GSS + 8 + tig * 2]    = d1[2];
        Gs[(row + 8) * GSS + 8 + tig * 2 + 1]= d1[3];
        Gs[row * GSS + 16 + tig * 2]          = d2[0];
        Gs[row * GSS + 16 + tig * 2 + 1]      = d2[1];
        Gs[(row + 8) * GSS + 16 + tig * 2]    = d2[2];
        Gs[(row + 8) * GSS + 16 + tig * 2 + 1]= d2[3];
    }
    __syncthreads();

    // ---- epilogue: fold G with parent features (threads 0..127, one k each) ----
    float sp = 0.f, sc = 0.f;
    if (tid < 128) {
        int k = kg * 128 + tid;
        float i00, i01, i02, i11, i12, i22;
        inv3sym(SP + (size_t)(b * K_ + k) * 9, i00, i01, i02, i11, i12, i22);
        const float* mp = muP + (size_t)(b * K_ + k) * 3;
        float p0 = mp[0], p1 = mp[1], p2 = mp[2];
        float w0 = i00 * p0 + i01 * p1 + i02 * p2;
        float w1 = i01 * p0 + i11 * p1 + i12 * p2;
        float w2 = i02 * p0 + i12 * p1 + i22 * p2;
        float r  = p0 * w0 + p1 * w1 + p2 * w2;
        const float* g = &Gs[tid * GSS];
        sp = g[0]*i00 + g[1]*i11 + g[2]*i22
           + 2.f*(g[3]*i01 + g[4]*i02 + g[5]*i12)
           - 2.f*(g[6]*w0 + g[7]*w1 + g[8]*w2)
           + g[9]*r;
        sc = g[10]*p0*p0 + g[11]*p1*p1 + g[12]*p2*p2
           + g[13]*p0*p1 + g[14]*p0*p2 + g[15]*p1*p2
           - 2.f*(g[16]*p0 + g[17]*p1 + g[18]*p2)
           + g[19];
    }
    float mv = (kg == 0) ? mval : 0.f;   // count each mask element once

    // ---- in-block reduction ----
#pragma unroll
    for (int off = 16; off; off >>= 1) {
        sp += __shfl_down_sync(0xffffffffu, sp, off);
        sc += __shfl_down_sync(0xffffffffu, sc, off);
        mv += __shfl_down_sync(0xffffffffu, mv, off);
    }
    if (lane == 0) { redP[wid] = sp; redC[wid] = sc; redM[wid] = mv; }
    __syncthreads();

    const int bid = (b * 4 + kg) * NSPLIT + x;
    if (tid == 0) {
        float tp = 0.f, tc = 0.f, tm = 0.f;
#pragma unroll
        for (int i = 0; i < 8; i++) { tp += redP[i]; tc += redC[i]; tm += redM[i]; }
        g_blkP[bid] = (double)tp;
        g_blkC[bid] = (double)tc;
        g_blkM[bid] = tm;
        __threadfence();
        unsigned t = atomicInc(&g_cnt, GRID_TOTAL - 1);
        sLast = (t == GRID_TOTAL - 1);
    }
    __syncthreads();

    // ---- last block: final reduction + output ----
    if (sLast) {
        __threadfence();
        __shared__ double fP[8], fC[8];
        __shared__ float  fM[8];
        double p = g_blkP[tid];   // 256 slots, 256 threads
        double c = g_blkC[tid];
        float  m = g_blkM[tid];
#pragma unroll
        for (int off = 16; off; off >>= 1) {
            p += __shfl_down_sync(0xffffffffu, p, off);
            c += __shfl_down_sync(0xffffffffu, c, off);
            m += __shfl_down_sync(0xffffffffu, m, off);
        }
        if (lane == 0) { fP[wid] = p; fC[wid] = c; fM[wid] = m; }
        __syncthreads();
        if (tid == 0) {
            double tp = 0.0, tc = 0.0;
            float  tm = 0.f;
#pragma unroll
            for (int i = 0; i < 8; i++) { tp += fP[i]; tc += fC[i]; tm += fM[i]; }
            double denom = (tm > 1.f) ? (double)tm : 1.0;
            out[0] = (float)((tp + tc) / denom);  // final_loss
            out[1] = (float)(tp / denom);          // dist_p_m
            out[2] = (float)(tc / denom);          // dist_c_m
        }
    }
}

extern "C" void kernel_launch(void* const* d_in, const int* in_sizes, int n_in,
                              void* d_out, int out_size) {
    const float* muC  = (const float*)d_in[0];
    const float* SC   = (const float*)d_in[1];
    const float* muP  = (const float*)d_in[2];
    const float* SP   = (const float*)d_in[3];
    const float* A    = (const float*)d_in[4];
    const float* mask = (const float*)d_in[5];

    dim3 grid(NSPLIT, 4, B_);
    loss_kernel<<<grid, NTHR>>>(muC, SC, muP, SP, A, mask, (float*)d_out);
}